// round 16
// baseline (speedup 1.0000x reference)
#include <cuda_runtime.h>
#include <cstdint>

// Problem constants (fixed by the dataset)
#define C_DIM 22
#define T_DIM 4000
#define M_DIM 16
#define B_DIM 16

// Tiling: 512-t double-buffered tiles, 8 tiles per item, 2 CTAs per SM.
#define TT    512
#define TPI   8          // ceil(4000/512), tail zero-filled
#define BLOCK 256

typedef unsigned long long u64;

// packed dual-fp32 FMA: d = a*b + c (elementwise on {lo,hi})
__device__ __forceinline__ u64 fma2(u64 a, u64 b, u64 c) {
    u64 d;
    asm("fma.rn.f32x2 %0, %1, %2, %3;" : "=l"(d) : "l"(a), "l"(b), "l"(c));
    return d;
}
__device__ __forceinline__ u64 dup2(float v) {
    u64 d; asm("mov.b64 %0, {%1, %1};" : "=l"(d) : "f"(v)); return d;
}

// Stage tile k of this item: 22 rows x 512 floats (45KB), 11 cp.async per thread.
// Zero-fills the t>=4000 tail (tile 7) without DRAM traffic.
__device__ __forceinline__ void stage_tile(float* dst, const float* __restrict__ gx,
                                           int k, int tid)
{
    const int tg = k * TT + ((tid & 127) << 2);      // global t of this 16B chunk
    const unsigned ss = (tg < T_DIM) ? 16u : 0u;     // src-size 0 => zero-fill
    const float* src = ss ? (gx + tg) : gx;          // clamp OOB address
    const int c0   = tid >> 7;                       // 0 or 1
    const int soff = (tid & 127) << 2;
    #pragma unroll
    for (int c = c0; c < C_DIM; c += 2) {
        unsigned sa = (unsigned)__cvta_generic_to_shared(dst + c * TT + soff);
        asm volatile("cp.async.cg.shared.global [%0], [%1], 16, %2;"
                     :: "r"(sa), "l"(src + c * T_DIM), "r"(ss));
    }
}

// One CTA per item (n*16+b). out[item,m] = log(diag[m]/sum_m diag[m]),
// diag[m] = sum_t (sum_c W[b,m,c]*x[c,t])^2. (The reference's 1/sqrt(T)
// scaling cancels in the ratio and is skipped.)
//
// Warp layout: mg = wid&1 selects 8 m's; th = wid>>1 selects a 128-t quarter.
// Each x element is read by only 2 warps -> smem crossbar traffic is 2x the
// tile bytes (90KB per 512-tile), half of R15's 4x, keeping LDS well under
// the FMA window. W stays in smem as dup'd f32x2 (broadcast LDS.128), so no
// W registers are held across the mainloop -> fits 2 CTAs/SM.
__global__ void __launch_bounds__(BLOCK, 2)
csp_kernel(const float* __restrict__ xfb, const float* __restrict__ WT,
           float* __restrict__ out)
{
    extern __shared__ float sm[];
    float* xb  = sm;                                  // 2 * 22*512 floats
    u64*   w2  = (u64*)(sm + 2 * C_DIM * TT);         // 22*16 dup'd pairs (16B-aligned)
    float* red = (float*)(w2 + C_DIM * M_DIM);        // 64 floats scratch

    const int tid  = threadIdx.x;
    const int lane = tid & 31;
    const int wid  = tid >> 5;
    const int mg   = wid & 1;                         // m-group: m in [8*mg, 8*mg+8)
    const int th   = wid >> 1;                        // t-quarter (128 t) within a tile

    const int item = blockIdx.x;
    const float* gx = xfb + (size_t)item * (C_DIM * T_DIM);

    // Kick off DRAM immediately.
    stage_tile(xb, gx, 0, tid);
    asm volatile("cp.async.commit_group;");

    // Fill w2[c*16+m] = dup{W[b,m,c]} while tile 0 is in flight.
    {
        const float* wb = WT + (size_t)(item & (B_DIM - 1)) * (M_DIM * C_DIM);
        #pragma unroll
        for (int idx = tid; idx < C_DIM * M_DIM; idx += BLOCK) {
            const int m = idx & 15, c = idx >> 4;
            w2[idx] = dup2(__ldg(wb + m * C_DIM + c));
        }
    }

    u64 acc[8];                                       // sum z^2 per m, packed over t
    #pragma unroll
    for (int j = 0; j < 8; j++) acc[j] = 0ull;

    const int tlb = (th << 7) + (lane << 1);          // base t within a tile
    const u64* wg = w2 + 8 * mg;                      // this warp's 8 m's

    #pragma unroll 1
    for (int k = 0; k < TPI; k++) {
        // Prefetch tile k+1 into the other slot (last read two barriers ago),
        // then wait for tile k. At k=7 drain everything.
        if (k + 1 < TPI) {
            stage_tile(xb + ((k + 1) & 1) * (C_DIM * TT), gx, k + 1, tid);
            asm volatile("cp.async.commit_group;");
            asm volatile("cp.async.wait_group 1;");
        } else {
            asm volatile("cp.async.wait_group 0;");
        }
        __syncthreads();   // tile k (and w2 at k=0) visible to all warps

        const float* xs = xb + (k & 1) * (C_DIM * TT) + tlb;

        u64 z[8][2];       // [m][t-pair], 16 independent FMA chains
        #pragma unroll
        for (int j = 0; j < 8; j++) z[j][0] = z[j][1] = 0ull;

        #pragma unroll
        for (int c = 0; c < C_DIM; c++) {
            const u64 xd0 = *(const u64*)(xs + c * TT);        // {t, t+1}
            const u64 xd1 = *(const u64*)(xs + c * TT + 64);   // {t+64, t+65}
            const ulonglong2* wc = (const ulonglong2*)(wg + c * 16);
            const ulonglong2 p0 = wc[0];   // m 8mg+0, 8mg+1 (broadcast LDS.128)
            const ulonglong2 p1 = wc[1];   // m 8mg+2, 8mg+3
            const ulonglong2 p2 = wc[2];   // m 8mg+4, 8mg+5
            const ulonglong2 p3 = wc[3];   // m 8mg+6, 8mg+7
            z[0][0] = fma2(p0.x, xd0, z[0][0]);  z[0][1] = fma2(p0.x, xd1, z[0][1]);
            z[1][0] = fma2(p0.y, xd0, z[1][0]);  z[1][1] = fma2(p0.y, xd1, z[1][1]);
            z[2][0] = fma2(p1.x, xd0, z[2][0]);  z[2][1] = fma2(p1.x, xd1, z[2][1]);
            z[3][0] = fma2(p1.y, xd0, z[3][0]);  z[3][1] = fma2(p1.y, xd1, z[3][1]);
            z[4][0] = fma2(p2.x, xd0, z[4][0]);  z[4][1] = fma2(p2.x, xd1, z[4][1]);
            z[5][0] = fma2(p2.y, xd0, z[5][0]);  z[5][1] = fma2(p2.y, xd1, z[5][1]);
            z[6][0] = fma2(p3.x, xd0, z[6][0]);  z[6][1] = fma2(p3.x, xd1, z[6][1]);
            z[7][0] = fma2(p3.y, xd0, z[7][0]);  z[7][1] = fma2(p3.y, xd1, z[7][1]);
        }
        #pragma unroll
        for (int j = 0; j < 8; j++) {
            acc[j] = fma2(z[j][0], z[j][0], acc[j]);
            acc[j] = fma2(z[j][1], z[j][1], acc[j]);
        }
        __syncthreads();   // all reads of this slot done before it is re-staged
    }

    // ---- reduction: per-warp diag contribution -> smem -> warp 0 finishes ----
    {
        float a[8];
        #pragma unroll
        for (int j = 0; j < 8; j++) {
            float lo, hi;
            asm("mov.b64 {%0, %1}, %2;" : "=f"(lo), "=f"(hi) : "l"(acc[j]));
            a[j] = lo + hi;
        }
        #pragma unroll
        for (int off = 16; off; off >>= 1) {
            #pragma unroll
            for (int j = 0; j < 8; j++)
                a[j] += __shfl_xor_sync(0xffffffffu, a[j], off);
        }
        if (lane == 0) {
            #pragma unroll
            for (int j = 0; j < 8; j++)
                red[wid * 8 + j] = a[j];
        }
    }
    __syncthreads();

    if (wid == 0) {
        // diag[m] for m = 8*mgi + j is spread over warps {mgi, mgi+2, mgi+4, mgi+6}.
        float d = 0.f;
        if (lane < M_DIM) {
            const int mgi = lane >> 3, j = lane & 7;
            d = red[(mgi + 0) * 8 + j] + red[(mgi + 2) * 8 + j]
              + red[(mgi + 4) * 8 + j] + red[(mgi + 6) * 8 + j];
        }
        float tot = d;
        #pragma unroll
        for (int off = 8; off; off >>= 1)
            tot += __shfl_xor_sync(0xffffffffu, tot, off);   // sums within 16-lane group
        if (lane < M_DIM)
            out[item * M_DIM + lane] = logf(d / tot);
    }
}

extern "C" void kernel_launch(void* const* d_in, const int* in_sizes, int n_in,
                              void* d_out, int out_size) {
    const float* xfb = (const float*)d_in[0];
    const float* WT  = (const float*)d_in[1];
    int nx = in_sizes[0];
    // Defensive: ensure xfb is the big tensor
    if (n_in >= 2 && in_sizes[0] < in_sizes[1]) {
        xfb = (const float*)d_in[1];
        WT  = (const float*)d_in[0];
        nx  = in_sizes[1];
    }
    const int n_items = nx / (C_DIM * T_DIM);        // = 1024 (N*B)

    const size_t smem_bytes =
        (size_t)(2 * C_DIM * TT) * sizeof(float)     // x double buffer (90,112 B)
        + (size_t)(C_DIM * M_DIM) * sizeof(u64)      // dup'd W pairs   ( 2,816 B)
        + 64 * sizeof(float);                        // reduction scratch

    cudaFuncSetAttribute((const void*)csp_kernel,
                         cudaFuncAttributeMaxDynamicSharedMemorySize,
                         (int)smem_bytes);

    csp_kernel<<<n_items, BLOCK, smem_bytes>>>(xfb, WT, (float*)d_out);
}

// round 17
// speedup vs baseline: 1.0362x; 1.0362x over previous
#include <cuda_runtime.h>
#include <cstdint>

// Problem constants (fixed by the dataset)
#define C_DIM 22
#define T_DIM 4000
#define M_DIM 16
#define B_DIM 16

// Tiling: 512-t double-buffered tiles, 8 tiles per item, 2 CTAs per SM.
#define TT          512
#define TPI         8           // 8 tiles; tile 7 holds 416 real t + 96 zeros
#define BLOCK       256
#define ROW_FULL    2048u       // 512 floats
#define ROW_TAIL    1664u       // (4000 - 7*512) = 416 floats
#define TAIL_FLOATS 416

typedef unsigned long long u64;

// packed dual-fp32 FMA: d = a*b + c (elementwise on {lo,hi})
__device__ __forceinline__ u64 fma2(u64 a, u64 b, u64 c) {
    u64 d;
    asm("fma.rn.f32x2 %0, %1, %2, %3;" : "=l"(d) : "l"(a), "l"(b), "l"(c));
    return d;
}
__device__ __forceinline__ u64 dup2(float v) {
    u64 d; asm("mov.b64 %0, {%1, %1};" : "=l"(d) : "f"(v)); return d;
}

__device__ __forceinline__ void mbar_init(unsigned mbar, unsigned cnt) {
    asm volatile("mbarrier.init.shared.b64 [%0], %1;" :: "r"(mbar), "r"(cnt) : "memory");
}
__device__ __forceinline__ void mbar_expect(unsigned mbar, unsigned bytes) {
    asm volatile("mbarrier.arrive.expect_tx.shared.b64 _, [%0], %1;"
                 :: "r"(mbar), "r"(bytes) : "memory");
}
__device__ __forceinline__ void mbar_wait(unsigned mbar, unsigned phase) {
    asm volatile(
        "{\n\t"
        ".reg .pred P;\n\t"
        "WAIT_%=:\n\t"
        "mbarrier.try_wait.parity.acquire.cta.shared::cta.b64 P, [%0], %1, 0x989680;\n\t"
        "@P bra.uni DONE_%=;\n\t"
        "bra.uni WAIT_%=;\n\t"
        "DONE_%=:\n\t"
        "}" :: "r"(mbar), "r"(phase) : "memory");
}
// 1D bulk async copy global->shared::cta with mbarrier completion.
__device__ __forceinline__ void bulk_cp(unsigned sdst, const void* gsrc,
                                        unsigned bytes, unsigned mbar) {
    asm volatile(
        "cp.async.bulk.shared::cta.global.mbarrier::complete_tx::bytes [%0], [%1], %2, [%3];"
        :: "r"(sdst), "l"(gsrc), "r"(bytes), "r"(mbar) : "memory");
}

// Issue the 22 row-copies for tile k of this item (one thread).
__device__ __forceinline__ void stage_tma(unsigned sdst_base, const float* __restrict__ gx,
                                          int k, unsigned mbar) {
    const unsigned bytes = (k == TPI - 1) ? ROW_TAIL : ROW_FULL;
    mbar_expect(mbar, bytes * C_DIM);
    const float* src = gx + k * TT;
    #pragma unroll
    for (int c = 0; c < C_DIM; c++)
        bulk_cp(sdst_base + c * (TT * 4), src + c * T_DIM, bytes, mbar);
}

// One CTA per item (n*16+b). out[item,m] = log(diag[m]/sum_m diag[m]),
// diag[m] = sum_t (sum_c W[b,m,c]*x[c,t])^2. The reference's 1/sqrt(T)
// scaling cancels in the ratio and is skipped.
//
// Staging is TMA bulk (off the L1tex/LSU pipe); compute reads x via one
// LDS.128 per c per warp (lane covers t..t+3) and dup'd-W via broadcast
// LDS.128. mg = wid&1 picks 8 m's, th = wid>>1 picks a 128-t quarter.
__global__ void __launch_bounds__(BLOCK, 2)
csp_kernel(const float* __restrict__ xfb, const float* __restrict__ WT,
           float* __restrict__ out)
{
    extern __shared__ float sm[];
    float* xb  = sm;                                  // 2 * 22*512 floats
    u64*   w2  = (u64*)(sm + 2 * C_DIM * TT);         // 22*16 dup'd pairs
    float* red = (float*)(w2 + C_DIM * M_DIM);        // 64 floats scratch
    u64*  mbar = (u64*)(red + 64);                    // 2 mbarriers

    const int tid  = threadIdx.x;
    const int lane = tid & 31;
    const int wid  = tid >> 5;
    const int mg   = wid & 1;                         // m-group: m in [8*mg, 8*mg+8)
    const int th   = wid >> 1;                        // 128-t quarter within a tile

    const int item = blockIdx.x;
    const float* gx = xfb + (size_t)item * (C_DIM * T_DIM);

    const unsigned xb_a = (unsigned)__cvta_generic_to_shared(xb);
    const unsigned bar0 = (unsigned)__cvta_generic_to_shared(mbar);
    const unsigned bar1 = bar0 + 8;

    if (tid == 0) { mbar_init(bar0, 1); mbar_init(bar1, 1); }
    asm volatile("fence.proxy.async.shared::cta;" ::: "memory");
    __syncthreads();    // mbarriers visible before any TMA touches them

    // Kick off DRAM immediately: tiles 0 and 1.
    if (tid == 0) {
        stage_tma(xb_a, gx, 0, bar0);
        stage_tma(xb_a + C_DIM * TT * 4, gx, 1, bar1);
    }

    // Fill w2[c*16+m] = dup{W[b,m,c]} while tiles are in flight.
    {
        const float* wb = WT + (size_t)(item & (B_DIM - 1)) * (M_DIM * C_DIM);
        #pragma unroll
        for (int idx = tid; idx < C_DIM * M_DIM; idx += BLOCK) {
            const int m = idx & 15, c = idx >> 4;
            w2[idx] = dup2(__ldg(wb + m * C_DIM + c));
        }
    }
    __syncthreads();    // w2 visible

    u64 acc[8];
    #pragma unroll
    for (int j = 0; j < 8; j++) acc[j] = 0ull;

    const int tlb = (th << 7) + (lane << 2);          // base t: lane covers t..t+3
    const u64* wg = w2 + 8 * mg;

    #pragma unroll 1
    for (int k = 0; k < TPI; k++) {
        mbar_wait((k & 1) ? bar1 : bar0, (k >> 1) & 1);   // tile k landed (acquire)

        const float* xs = xb + (k & 1) * (C_DIM * TT) + tlb;

        u64 z[8][2];      // [m][t-pair], 16 independent FMA chains
        #pragma unroll
        for (int j = 0; j < 8; j++) z[j][0] = z[j][1] = 0ull;

        #pragma unroll
        for (int c = 0; c < C_DIM; c++) {
            const ulonglong2 xv = *(const ulonglong2*)(xs + c * TT); // {t,t+1},{t+2,t+3}
            const ulonglong2* wc = (const ulonglong2*)(wg + c * 16);
            const ulonglong2 p0 = wc[0];   // m 8mg+0, 8mg+1 (broadcast)
            const ulonglong2 p1 = wc[1];
            const ulonglong2 p2 = wc[2];
            const ulonglong2 p3 = wc[3];
            z[0][0] = fma2(p0.x, xv.x, z[0][0]);  z[0][1] = fma2(p0.x, xv.y, z[0][1]);
            z[1][0] = fma2(p0.y, xv.x, z[1][0]);  z[1][1] = fma2(p0.y, xv.y, z[1][1]);
            z[2][0] = fma2(p1.x, xv.x, z[2][0]);  z[2][1] = fma2(p1.x, xv.y, z[2][1]);
            z[3][0] = fma2(p1.y, xv.x, z[3][0]);  z[3][1] = fma2(p1.y, xv.y, z[3][1]);
            z[4][0] = fma2(p2.x, xv.x, z[4][0]);  z[4][1] = fma2(p2.x, xv.y, z[4][1]);
            z[5][0] = fma2(p2.y, xv.x, z[5][0]);  z[5][1] = fma2(p2.y, xv.y, z[5][1]);
            z[6][0] = fma2(p3.x, xv.x, z[6][0]);  z[6][1] = fma2(p3.x, xv.y, z[6][1]);
            z[7][0] = fma2(p3.y, xv.x, z[7][0]);  z[7][1] = fma2(p3.y, xv.y, z[7][1]);
        }
        #pragma unroll
        for (int j = 0; j < 8; j++) {
            acc[j] = fma2(z[j][0], z[j][0], acc[j]);
            acc[j] = fma2(z[j][1], z[j][1], acc[j]);
        }
        __syncthreads();   // all warps done reading slot k&1

        const int kn = k + 2;
        if (kn < TPI) {
            if (kn == TPI - 1) {
                // Zero the tail region of this slot (tile 7 copies only 416
                // floats/row). Prior tile-5 TMA writes here are ordered before
                // these STS by this iteration's acquire-wait; these STS are
                // ordered before tile-7's readers by the k+1 __syncthreads.
                float* slot = xb + (k & 1) * (C_DIM * TT);
                #pragma unroll
                for (int i = tid; i < C_DIM * (TT - TAIL_FLOATS); i += BLOCK) {
                    const int c = i / (TT - TAIL_FLOATS);
                    const int o = i - c * (TT - TAIL_FLOATS);
                    slot[c * TT + TAIL_FLOATS + o] = 0.f;
                }
            }
            if (tid == 0)
                stage_tma(xb_a + (k & 1) * (C_DIM * TT * 4), gx, kn,
                          (k & 1) ? bar1 : bar0);
        }
    }

    // ---- reduction: per-warp diag contribution -> smem -> warp 0 finishes ----
    {
        float a[8];
        #pragma unroll
        for (int j = 0; j < 8; j++) {
            float lo, hi;
            asm("mov.b64 {%0, %1}, %2;" : "=f"(lo), "=f"(hi) : "l"(acc[j]));
            a[j] = lo + hi;
        }
        #pragma unroll
        for (int off = 16; off; off >>= 1) {
            #pragma unroll
            for (int j = 0; j < 8; j++)
                a[j] += __shfl_xor_sync(0xffffffffu, a[j], off);
        }
        if (lane == 0) {
            #pragma unroll
            for (int j = 0; j < 8; j++)
                red[wid * 8 + j] = a[j];
        }
    }
    __syncthreads();

    if (wid == 0) {
        // diag[m] for m = 8*mgi + j is spread over warps {mgi, mgi+2, mgi+4, mgi+6}.
        float d = 0.f;
        if (lane < M_DIM) {
            const int mgi = lane >> 3, j = lane & 7;
            d = red[(mgi + 0) * 8 + j] + red[(mgi + 2) * 8 + j]
              + red[(mgi + 4) * 8 + j] + red[(mgi + 6) * 8 + j];
        }
        float tot = d;
        #pragma unroll
        for (int off = 8; off; off >>= 1)
            tot += __shfl_xor_sync(0xffffffffu, tot, off);   // sums the 16-lane group
        if (lane < M_DIM)
            out[item * M_DIM + lane] = logf(d / tot);
    }
}

extern "C" void kernel_launch(void* const* d_in, const int* in_sizes, int n_in,
                              void* d_out, int out_size) {
    const float* xfb = (const float*)d_in[0];
    const float* WT  = (const float*)d_in[1];
    int nx = in_sizes[0];
    // Defensive: ensure xfb is the big tensor
    if (n_in >= 2 && in_sizes[0] < in_sizes[1]) {
        xfb = (const float*)d_in[1];
        WT  = (const float*)d_in[0];
        nx  = in_sizes[1];
    }
    const int n_items = nx / (C_DIM * T_DIM);        // = 1024 (N*B)

    const size_t smem_bytes =
        (size_t)(2 * C_DIM * TT) * sizeof(float)     // x double buffer (90,112 B)
        + (size_t)(C_DIM * M_DIM) * sizeof(u64)      // dup'd W pairs   ( 2,816 B)
        + 64 * sizeof(float)                         // reduction scratch
        + 2 * sizeof(u64);                           // mbarriers

    cudaFuncSetAttribute((const void*)csp_kernel,
                         cudaFuncAttributeMaxDynamicSharedMemorySize,
                         (int)smem_bytes);

    csp_kernel<<<n_items, BLOCK, smem_bytes>>>(xfb, WT, (float*)d_out);
}